// round 12
// baseline (speedup 1.0000x reference)
#include <cuda_runtime.h>
#include <cuda_fp16.h>
#include <cstdint>

// Problem constants
#define BB 256
#define DD 10
#define PP 1152
#define OO 16
#define DOX 160            // D*O
#define II 8
#define PCH 8              // p per chunk in k_uhat
#define NCH (PP / PCH)     // 144
#define BGRP 64            // b per CTA in k_uhat
#define NBG (BB / BGRP)    // 4
#define CSZ 4              // cluster size (CTAs per b)
#define QP (PP / CSZ)      // 288 p per quarter
#define QCH (NCH / CSZ)    // 36 s1p chunks per quarter
#define NIT (QP / 16)      // 18 warp-iterations per pass (2 p per iter)
#define NSEG 3             // fp16 accumulation segments per pass
#define SEGL (NIT / NSEG)  // 6 iterations per segment

// Scratch (u_hat padded by one prefetch row-group so tail prefetch is safe)
__device__ __half g_uhat_h[(size_t)BB * PP * DOX + 16 * DOX];  // 94.4 MB
__device__ float g_s1p[(size_t)BB * NCH * DOX];                // 23.6 MB

// ---------------------------------------------------------------------------
// Kernel 1: u_hat = W.x (fp16 math + store) + per-chunk fp32 s1 partials.
// Grid (NCH, NBG) x 160 threads.
// ---------------------------------------------------------------------------
__global__ void __launch_bounds__(DOX) k_uhat(const float* __restrict__ x,
                                              const float* __restrict__ W) {
    const int c = blockIdx.x;
    const int t = threadIdx.x;
    const int d = t >> 4;
    const int o = t & 15;
    const int p0 = c * PCH;
    const int b0 = blockIdx.y * BGRP;

    __half2 w2[PCH][4];
#pragma unroll
    for (int ps = 0; ps < PCH; ps++) {
        const float4* wp = reinterpret_cast<const float4*>(
            W + (((size_t)d * PP + (size_t)(p0 + ps)) * OO + o) * II);
        float4 wa = wp[0], wb = wp[1];
        w2[ps][0] = __floats2half2_rn(wa.x, wa.y);
        w2[ps][1] = __floats2half2_rn(wa.z, wa.w);
        w2[ps][2] = __floats2half2_rn(wb.x, wb.y);
        w2[ps][3] = __floats2half2_rn(wb.z, wb.w);
    }

    __shared__ uint4 xs4[BGRP * PCH];   // 8 KB
    for (int idx = t; idx < BGRP * PCH; idx += DOX) {
        int bb = idx >> 3;
        int ps = idx & 7;
        const float4* xp = reinterpret_cast<const float4*>(
            x + ((size_t)(b0 + bb) * PP + (size_t)(p0 + ps)) * II);
        float4 xa = xp[0], xb = xp[1];
        uint4 h;
        reinterpret_cast<__half2*>(&h)[0] = __floats2half2_rn(xa.x, xa.y);
        reinterpret_cast<__half2*>(&h)[1] = __floats2half2_rn(xa.z, xa.w);
        reinterpret_cast<__half2*>(&h)[2] = __floats2half2_rn(xb.x, xb.y);
        reinterpret_cast<__half2*>(&h)[3] = __floats2half2_rn(xb.z, xb.w);
        xs4[idx] = h;
    }
    __syncthreads();

    for (int bb = 0; bb < BGRP; bb++) {
        float acc = 0.f;
        __half* ud = g_uhat_h + ((size_t)(b0 + bb) * PP + p0) * DOX + t;
#pragma unroll
        for (int ps = 0; ps < PCH; ps++) {
            uint4 xr = xs4[bb * PCH + ps];
            __half2 a = __hmul2(w2[ps][0], *reinterpret_cast<__half2*>(&xr.x));
            a = __hfma2(w2[ps][1], *reinterpret_cast<__half2*>(&xr.y), a);
            a = __hfma2(w2[ps][2], *reinterpret_cast<__half2*>(&xr.z), a);
            a = __hfma2(w2[ps][3], *reinterpret_cast<__half2*>(&xr.w), a);
            __half u = __hadd(__low2half(a), __high2half(a));
            ud[(size_t)ps * DOX] = u;
            acc += __half2float(u);
        }
        g_s1p[((size_t)(b0 + bb) * NCH + c) * DOX + t] = acc;
    }
}

// ---------------------------------------------------------------------------
// Helpers
// ---------------------------------------------------------------------------
__device__ __forceinline__ unsigned smem_u32(const void* p) {
    unsigned a;
    asm("{ .reg .u64 tmp; cvta.to.shared.u64 tmp, %1; cvt.u32.u64 %0, tmp; }"
        : "=r"(a) : "l"(p));
    return a;
}
__device__ __forceinline__ float ld_peer_f32(unsigned local_addr, unsigned rank) {
    unsigned ra;
    asm("mapa.shared::cluster.u32 %0, %1, %2;" : "=r"(ra) : "r"(local_addr), "r"(rank));
    float v;
    asm volatile("ld.shared::cluster.f32 %0, [%1];" : "=f"(v) : "r"(ra));
    return v;
}
__device__ __forceinline__ void cluster_sync() {
    asm volatile("barrier.cluster.arrive.aligned;" ::: "memory");
    asm volatile("barrier.cluster.wait.aligned;" ::: "memory");
}
__device__ __forceinline__ float squash_scale16(float s) {
    float sq = s * s;
    sq += __shfl_xor_sync(0xffffffffu, sq, 1);
    sq += __shfl_xor_sync(0xffffffffu, sq, 2);
    sq += __shfl_xor_sync(0xffffffffu, sq, 4);
    sq += __shfl_xor_sync(0xffffffffu, sq, 8);
    return sq / ((1.f + sq) * sqrtf(sq + 1e-7f));
}
__device__ __forceinline__ float expp(float xv) {
    float r = fmaf(xv, 1.f / 24.f, 1.f / 6.f);
    r = fmaf(r, xv, 0.5f);
    r = fmaf(r, xv, 1.f);
    r = fmaf(r, xv, 1.f);
    return r;
}

// ---------------------------------------------------------------------------
// Kernel 2: fused routing, 4-CTA cluster per b (each CTA owns a p-quarter).
// Lane = ph*16 + d (d<10 valid); lane owns one full d-row of one p;
// warp handles 2 p per iteration. fp16 segment accumulation flushed into a
// per-(warp,ph) smem slab (no fp32 accumulator registers).
// Grid CSZ*BB x 256 threads.
// ---------------------------------------------------------------------------
__global__ void __launch_bounds__(256, 5) __cluster_dims__(CSZ, 1, 1)
k_route(float* __restrict__ out) {
    const int b = blockIdx.x >> 2;
    const unsigned q = blockIdx.x & 3;
    const int t = threadIdx.x;
    const int lane = t & 31;
    const int wid = t >> 5;              // 0..7
    const int ph = lane >> 4;            // p parity within warp
    const int d = lane & 15;
    const bool valid = d < DD;
    const int dd = valid ? d : 0;
    const int row = wid * 2 + ph;        // 0..15, sred slab row

    __shared__ float vsm[DOX];
    __shared__ float v1sm[DOX];
    __shared__ float sred[16 * DOX];     // 10 KB: per-(warp,ph) partials
    __shared__ float xbuf[3][DOX];

    // ---- stage 0: v1 from s1p (my quarter of chunks) ----
    {
        float s = 0.f;
        if (t < DOX) {
            const float* sp = g_s1p + ((size_t)b * NCH + q * QCH) * DOX + t;
#pragma unroll 4
            for (int c = 0; c < QCH; c++) s += sp[(size_t)c * DOX];
            xbuf[0][t] = s;
        }
        cluster_sync();
        if (t < DOX) {
            unsigned addr = smem_u32(&xbuf[0][t]);
            float tot = 0.f;
#pragma unroll
            for (unsigned r = 0; r < CSZ; r++) tot += ld_peer_f32(addr, r);
            tot *= 0.1f;
            float v = tot * squash_scale16(tot);
            v1sm[t] = v;
            vsm[t] = v;
        }
        __syncthreads();
    }

    const __half* ulane = g_uhat_h + ((size_t)b * PP + (size_t)q * QP
                                      + (size_t)row) * DOX + dd * OO;
    const __half2 hzero = __half2half2(__ushort_as_half((unsigned short)0));

    for (int pass = 0; pass < 2; pass++) {
        __half2 vh[8];
#pragma unroll
        for (int j = 0; j < 8; j++)
            vh[j] = __floats2half2_rn(vsm[dd * OO + 2 * j], vsm[dd * OO + 2 * j + 1]);

        const __half* up = ulane;
        uint4 ra = *reinterpret_cast<const uint4*>(up);
        uint4 rb = *reinterpret_cast<const uint4*>(up + 8);

        float4* slab = reinterpret_cast<float4*>(&sred[row * DOX + dd * OO]);

#pragma unroll
        for (int seg = 0; seg < NSEG; seg++) {
            __half2 sa16[8];
#pragma unroll
            for (int j = 0; j < 8; j++) sa16[j] = hzero;

#pragma unroll
            for (int k = 0; k < SEGL; k++) {
                const __half* nup = up + (size_t)16 * DOX;
                uint4 na = *reinterpret_cast<const uint4*>(nup);
                uint4 nb = *reinterpret_cast<const uint4*>(nup + 8);

                __half2 u2[8];
                u2[0] = *reinterpret_cast<const __half2*>(&ra.x);
                u2[1] = *reinterpret_cast<const __half2*>(&ra.y);
                u2[2] = *reinterpret_cast<const __half2*>(&ra.z);
                u2[3] = *reinterpret_cast<const __half2*>(&ra.w);
                u2[4] = *reinterpret_cast<const __half2*>(&rb.x);
                u2[5] = *reinterpret_cast<const __half2*>(&rb.y);
                u2[6] = *reinterpret_cast<const __half2*>(&rb.z);
                u2[7] = *reinterpret_cast<const __half2*>(&rb.w);

                __half2 h0 = __hmul2(u2[0], vh[0]);
                __half2 h1 = __hmul2(u2[1], vh[1]);
                h0 = __hfma2(u2[2], vh[2], h0);
                h1 = __hfma2(u2[3], vh[3], h1);
                h0 = __hfma2(u2[4], vh[4], h0);
                h1 = __hfma2(u2[5], vh[5], h1);
                h0 = __hfma2(u2[6], vh[6], h0);
                h1 = __hfma2(u2[7], vh[7], h1);
                float2 hf = __half22float2(__hadd2(h0, h1));
                float uv = hf.x + hf.y;

                float e = valid ? expp(uv) : 0.f;
                float tot = e;
                tot += __shfl_xor_sync(0xffffffffu, tot, 1);
                tot += __shfl_xor_sync(0xffffffffu, tot, 2);
                tot += __shfl_xor_sync(0xffffffffu, tot, 4);
                tot += __shfl_xor_sync(0xffffffffu, tot, 8);
                float cc = __fdividef(e, tot);

                __half2 cch = __half2half2(__float2half_rn(cc));
#pragma unroll
                for (int j = 0; j < 8; j++)
                    sa16[j] = __hfma2(cch, u2[j], sa16[j]);

                ra = na; rb = nb; up = nup;
            }

            // flush segment into smem slab (seg0 overwrites, later segs add)
            if (valid) {
                float2 f0 = __half22float2(sa16[0]), f1 = __half22float2(sa16[1]);
                float2 f2 = __half22float2(sa16[2]), f3 = __half22float2(sa16[3]);
                float2 f4 = __half22float2(sa16[4]), f5 = __half22float2(sa16[5]);
                float2 f6 = __half22float2(sa16[6]), f7 = __half22float2(sa16[7]);
                float4 a0 = make_float4(f0.x, f0.y, f1.x, f1.y);
                float4 a1 = make_float4(f2.x, f2.y, f3.x, f3.y);
                float4 a2 = make_float4(f4.x, f4.y, f5.x, f5.y);
                float4 a3 = make_float4(f6.x, f6.y, f7.x, f7.y);
                if (seg == 0) {
                    slab[0] = a0; slab[1] = a1; slab[2] = a2; slab[3] = a3;
                } else {
                    float4 b0 = slab[0], b1 = slab[1], b2 = slab[2], b3 = slab[3];
                    slab[0] = make_float4(b0.x + a0.x, b0.y + a0.y, b0.z + a0.z, b0.w + a0.w);
                    slab[1] = make_float4(b1.x + a1.x, b1.y + a1.y, b1.z + a1.z, b1.w + a1.w);
                    slab[2] = make_float4(b2.x + a2.x, b2.y + a2.y, b2.z + a2.z, b2.w + a2.w);
                    slab[3] = make_float4(b3.x + a3.x, b3.y + a3.y, b3.z + a3.z, b3.w + a3.w);
                }
            }
        }
        __syncthreads();

        float s = 0.f;
        if (t < DOX) {
#pragma unroll
            for (int ww = 0; ww < 16; ww++) s += sred[ww * DOX + t];
            xbuf[pass + 1][t] = s;
        }
        cluster_sync();
        if (t < DOX) {
            unsigned addr = smem_u32(&xbuf[pass + 1][t]);
            float tot = 0.f;
#pragma unroll
            for (unsigned r = 0; r < CSZ; r++) tot += ld_peer_f32(addr, r);
            float v = tot * squash_scale16(tot);
            if (pass == 0) vsm[t] = v1sm[t] + v;
            else if (q == 0) out[(size_t)b * DOX + t] = v;
        }
        __syncthreads();
    }
    cluster_sync();   // keep smem alive until peers' last DSMEM reads complete
}

// ---------------------------------------------------------------------------
extern "C" void kernel_launch(void* const* d_in, const int* in_sizes, int n_in,
                              void* d_out, int out_size) {
    const float* x = (const float*)d_in[0];   // [256, 1152, 8]
    const float* W = (const float*)d_in[1];   // [1, 10, 1152, 16, 8]
    float* out = (float*)d_out;               // [256, 10, 16]
    (void)in_sizes; (void)n_in; (void)out_size;

    k_uhat<<<dim3(NCH, NBG), DOX>>>(x, W);
    k_route<<<CSZ * BB, 256>>>(out);
}

// round 13
// speedup vs baseline: 1.0729x; 1.0729x over previous
#include <cuda_runtime.h>
#include <cuda_fp16.h>
#include <cstdint>

// Problem constants
#define BB 256
#define DD 10
#define PP 1152
#define OO 16
#define DOX 160            // D*O
#define II 8
#define PCH 8              // p per chunk in k_uhat
#define NCH (PP / PCH)     // 144
#define BGRP 64            // b per CTA in k_uhat
#define NBG (BB / BGRP)    // 4
#define HP (PP / 2)        // 576 p per cluster half
#define HCH (NCH / 2)      // 72 s1p chunks per half
#define NDS (HP / 32)      // 18 double-steps per pass (2x2 p per warp-step)
#define NSEG 6             // fp16 accumulation segments per pass
#define SEGL (NDS / NSEG)  // 3 double-steps per segment (6 fp16 adds/slot)

// Scratch (u_hat padded by 64 rows so deep prefetch stays in-bounds)
__device__ __half g_uhat_h[(size_t)BB * PP * DOX + 64 * DOX];  // 94.4 MB
__device__ float g_s1p[(size_t)BB * NCH * DOX];                // 23.6 MB

// ---------------------------------------------------------------------------
// Kernel 1: u_hat = W.x (fp16 math + store) + per-chunk fp32 s1 partials.
// Grid (NCH, NBG) x 160 threads.  (round-10/11 version, ~23 us)
// ---------------------------------------------------------------------------
__global__ void __launch_bounds__(DOX) k_uhat(const float* __restrict__ x,
                                              const float* __restrict__ W) {
    const int c = blockIdx.x;
    const int t = threadIdx.x;
    const int d = t >> 4;
    const int o = t & 15;
    const int p0 = c * PCH;
    const int b0 = blockIdx.y * BGRP;

    __half2 w2[PCH][4];
#pragma unroll
    for (int ps = 0; ps < PCH; ps++) {
        const float4* wp = reinterpret_cast<const float4*>(
            W + (((size_t)d * PP + (size_t)(p0 + ps)) * OO + o) * II);
        float4 wa = wp[0], wb = wp[1];
        w2[ps][0] = __floats2half2_rn(wa.x, wa.y);
        w2[ps][1] = __floats2half2_rn(wa.z, wa.w);
        w2[ps][2] = __floats2half2_rn(wb.x, wb.y);
        w2[ps][3] = __floats2half2_rn(wb.z, wb.w);
    }

    __shared__ uint4 xs4[BGRP * PCH];   // 8 KB
    for (int idx = t; idx < BGRP * PCH; idx += DOX) {
        int bb = idx >> 3;
        int ps = idx & 7;
        const float4* xp = reinterpret_cast<const float4*>(
            x + ((size_t)(b0 + bb) * PP + (size_t)(p0 + ps)) * II);
        float4 xa = xp[0], xb = xp[1];
        uint4 h;
        reinterpret_cast<__half2*>(&h)[0] = __floats2half2_rn(xa.x, xa.y);
        reinterpret_cast<__half2*>(&h)[1] = __floats2half2_rn(xa.z, xa.w);
        reinterpret_cast<__half2*>(&h)[2] = __floats2half2_rn(xb.x, xb.y);
        reinterpret_cast<__half2*>(&h)[3] = __floats2half2_rn(xb.z, xb.w);
        xs4[idx] = h;
    }
    __syncthreads();

    for (int bb = 0; bb < BGRP; bb++) {
        float acc = 0.f;
        __half* ud = g_uhat_h + ((size_t)(b0 + bb) * PP + p0) * DOX + t;
#pragma unroll
        for (int ps = 0; ps < PCH; ps++) {
            uint4 xr = xs4[bb * PCH + ps];
            __half2 a = __hmul2(w2[ps][0], *reinterpret_cast<__half2*>(&xr.x));
            a = __hfma2(w2[ps][1], *reinterpret_cast<__half2*>(&xr.y), a);
            a = __hfma2(w2[ps][2], *reinterpret_cast<__half2*>(&xr.z), a);
            a = __hfma2(w2[ps][3], *reinterpret_cast<__half2*>(&xr.w), a);
            __half u = __hadd(__low2half(a), __high2half(a));
            ud[(size_t)ps * DOX] = u;
            acc += __half2float(u);
        }
        g_s1p[((size_t)(b0 + bb) * NCH + c) * DOX + t] = acc;
    }
}

// ---------------------------------------------------------------------------
// Helpers
// ---------------------------------------------------------------------------
__device__ __forceinline__ unsigned smem_u32(const void* p) {
    unsigned a;
    asm("{ .reg .u64 tmp; cvta.to.shared.u64 tmp, %1; cvt.u32.u64 %0, tmp; }"
        : "=r"(a) : "l"(p));
    return a;
}
__device__ __forceinline__ float ld_peer_f32(unsigned local_addr, unsigned rank) {
    unsigned ra;
    asm("mapa.shared::cluster.u32 %0, %1, %2;" : "=r"(ra) : "r"(local_addr), "r"(rank));
    float v;
    asm volatile("ld.shared::cluster.f32 %0, [%1];" : "=f"(v) : "r"(ra));
    return v;
}
__device__ __forceinline__ void cluster_sync() {
    asm volatile("barrier.cluster.arrive.aligned;" ::: "memory");
    asm volatile("barrier.cluster.wait.aligned;" ::: "memory");
}
__device__ __forceinline__ float squash_scale16(float s) {
    float sq = s * s;
    sq += __shfl_xor_sync(0xffffffffu, sq, 1);
    sq += __shfl_xor_sync(0xffffffffu, sq, 2);
    sq += __shfl_xor_sync(0xffffffffu, sq, 4);
    sq += __shfl_xor_sync(0xffffffffu, sq, 8);
    return sq / ((1.f + sq) * sqrtf(sq + 1e-7f));
}
__device__ __forceinline__ float expp(float xv) {
    float r = fmaf(xv, 1.f / 24.f, 1.f / 6.f);
    r = fmaf(r, xv, 0.5f);
    r = fmaf(r, xv, 1.f);
    r = fmaf(r, xv, 1.f);
    return r;
}
__device__ __forceinline__ void unp8(__half2* u, uint4 ra, uint4 rb) {
    u[0] = *reinterpret_cast<const __half2*>(&ra.x);
    u[1] = *reinterpret_cast<const __half2*>(&ra.y);
    u[2] = *reinterpret_cast<const __half2*>(&ra.z);
    u[3] = *reinterpret_cast<const __half2*>(&ra.w);
    u[4] = *reinterpret_cast<const __half2*>(&rb.x);
    u[5] = *reinterpret_cast<const __half2*>(&rb.y);
    u[6] = *reinterpret_cast<const __half2*>(&rb.z);
    u[7] = *reinterpret_cast<const __half2*>(&rb.w);
}
__device__ __forceinline__ float dot16(const __half2* u, const __half2* vh) {
    __half2 h0 = __hmul2(u[0], vh[0]);
    __half2 h1 = __hmul2(u[1], vh[1]);
    h0 = __hfma2(u[2], vh[2], h0);
    h1 = __hfma2(u[3], vh[3], h1);
    h0 = __hfma2(u[4], vh[4], h0);
    h1 = __hfma2(u[5], vh[5], h1);
    h0 = __hfma2(u[6], vh[6], h0);
    h1 = __hfma2(u[7], vh[7], h1);
    float2 hf = __half22float2(__hadd2(h0, h1));
    return hf.x + hf.y;
}

// ---------------------------------------------------------------------------
// Kernel 2: fused routing, 2-CTA cluster per b. Lane = ph*16 + d; lane owns
// one full d-row (16 halfs). Warp processes 2x2 p per double-step with the
// two softmax chains explicitly interleaved. Segment flushes go to a
// per-(warp,ph) smem slab (no fp32 accumulator registers).
// Grid 2*BB x 256 threads.
// ---------------------------------------------------------------------------
__global__ void __launch_bounds__(256, 4) __cluster_dims__(2, 1, 1)
k_route(float* __restrict__ out) {
    const int b = blockIdx.x >> 1;
    const unsigned half = blockIdx.x & 1;
    const unsigned peer = half ^ 1u;
    const int t = threadIdx.x;
    const int lane = t & 31;
    const int wid = t >> 5;              // 0..7
    const int ph = lane >> 4;            // p parity within warp
    const int d = lane & 15;
    const bool valid = d < DD;
    const int dd = valid ? d : 0;
    const int row = wid * 2 + ph;        // 0..15 slab row

    __shared__ float vsm[DOX];
    __shared__ float v1sm[DOX];
    __shared__ float sred[16 * DOX];     // 10 KB
    __shared__ float xbuf[3][DOX];

    // ---- stage 0: v1 from s1p (my half of chunks) ----
    {
        float s = 0.f;
        if (t < DOX) {
            const float* sp = g_s1p + ((size_t)b * NCH + half * HCH) * DOX + t;
#pragma unroll 4
            for (int c = 0; c < HCH; c++) s += sp[(size_t)c * DOX];
            xbuf[0][t] = s;
        }
        cluster_sync();
        if (t < DOX) {
            float tot = s + ld_peer_f32(smem_u32(&xbuf[0][t]), peer);
            tot *= 0.1f;
            float v = tot * squash_scale16(tot);
            v1sm[t] = v;
            vsm[t] = v;
        }
        __syncthreads();
    }

    // A row: p = 32*step + row;  B row: A + 16.
    const __half* ulane = g_uhat_h + ((size_t)b * PP + (size_t)half * HP
                                      + (size_t)row) * DOX + dd * OO;
    const __half2 hzero = __half2half2(__ushort_as_half((unsigned short)0));

    for (int pass = 0; pass < 2; pass++) {
        __half2 vh[8];
#pragma unroll
        for (int j = 0; j < 8; j++)
            vh[j] = __floats2half2_rn(vsm[dd * OO + 2 * j], vsm[dd * OO + 2 * j + 1]);

        const __half* up = ulane;
        uint4 raA = *reinterpret_cast<const uint4*>(up);
        uint4 rbA = *reinterpret_cast<const uint4*>(up + 8);
        uint4 raB = *reinterpret_cast<const uint4*>(up + 16 * DOX);
        uint4 rbB = *reinterpret_cast<const uint4*>(up + 16 * DOX + 8);

        float4* slab = reinterpret_cast<float4*>(&sred[row * DOX + dd * OO]);

#pragma unroll
        for (int seg = 0; seg < NSEG; seg++) {
            __half2 sa16[8];
#pragma unroll
            for (int j = 0; j < 8; j++) sa16[j] = hzero;

#pragma unroll
            for (int k = 0; k < SEGL; k++) {
                // prefetch next double-step (rows +32); padded tail -> safe
                const __half* nup = up + (size_t)32 * DOX;
                uint4 naA = *reinterpret_cast<const uint4*>(nup);
                uint4 nbA = *reinterpret_cast<const uint4*>(nup + 8);
                uint4 naB = *reinterpret_cast<const uint4*>(nup + 16 * DOX);
                uint4 nbB = *reinterpret_cast<const uint4*>(nup + 16 * DOX + 8);

                __half2 uA[8], uB[8];
                unp8(uA, raA, rbA);
                unp8(uB, raB, rbB);

                float uvA = dot16(uA, vh);
                float uvB = dot16(uB, vh);
                float eA = valid ? expp(uvA) : 0.f;
                float eB = valid ? expp(uvB) : 0.f;

                // two interleaved 4-step butterflies over the 16-lane d-group
                float tA = eA, tB = eB;
                tA += __shfl_xor_sync(0xffffffffu, tA, 1);
                tB += __shfl_xor_sync(0xffffffffu, tB, 1);
                tA += __shfl_xor_sync(0xffffffffu, tA, 2);
                tB += __shfl_xor_sync(0xffffffffu, tB, 2);
                tA += __shfl_xor_sync(0xffffffffu, tA, 4);
                tB += __shfl_xor_sync(0xffffffffu, tB, 4);
                tA += __shfl_xor_sync(0xffffffffu, tA, 8);
                tB += __shfl_xor_sync(0xffffffffu, tB, 8);

                float ccA = __fdividef(eA, tA);
                float ccB = __fdividef(eB, tB);
                __half2 chA = __half2half2(__float2half_rn(ccA));
                __half2 chB = __half2half2(__float2half_rn(ccB));
#pragma unroll
                for (int j = 0; j < 8; j++) sa16[j] = __hfma2(chA, uA[j], sa16[j]);
#pragma unroll
                for (int j = 0; j < 8; j++) sa16[j] = __hfma2(chB, uB[j], sa16[j]);

                raA = naA; rbA = nbA; raB = naB; rbB = nbB; up = nup;
            }

            // flush segment into smem slab (seg0 overwrites, later segs add)
            if (valid) {
                float2 f0 = __half22float2(sa16[0]), f1 = __half22float2(sa16[1]);
                float2 f2 = __half22float2(sa16[2]), f3 = __half22float2(sa16[3]);
                float2 f4 = __half22float2(sa16[4]), f5 = __half22float2(sa16[5]);
                float2 f6 = __half22float2(sa16[6]), f7 = __half22float2(sa16[7]);
                float4 a0 = make_float4(f0.x, f0.y, f1.x, f1.y);
                float4 a1 = make_float4(f2.x, f2.y, f3.x, f3.y);
                float4 a2 = make_float4(f4.x, f4.y, f5.x, f5.y);
                float4 a3 = make_float4(f6.x, f6.y, f7.x, f7.y);
                if (seg == 0) {
                    slab[0] = a0; slab[1] = a1; slab[2] = a2; slab[3] = a3;
                } else {
                    float4 b0 = slab[0], b1 = slab[1], b2 = slab[2], b3 = slab[3];
                    slab[0] = make_float4(b0.x + a0.x, b0.y + a0.y, b0.z + a0.z, b0.w + a0.w);
                    slab[1] = make_float4(b1.x + a1.x, b1.y + a1.y, b1.z + a1.z, b1.w + a1.w);
                    slab[2] = make_float4(b2.x + a2.x, b2.y + a2.y, b2.z + a2.z, b2.w + a2.w);
                    slab[3] = make_float4(b3.x + a3.x, b3.y + a3.y, b3.z + a3.z, b3.w + a3.w);
                }
            }
        }
        __syncthreads();

        float s = 0.f;
        if (t < DOX) {
#pragma unroll
            for (int ww = 0; ww < 16; ww++) s += sred[ww * DOX + t];
            xbuf[pass + 1][t] = s;
        }
        cluster_sync();
        if (t < DOX) {
            float tot = s + ld_peer_f32(smem_u32(&xbuf[pass + 1][t]), peer);
            float v = tot * squash_scale16(tot);
            if (pass == 0) vsm[t] = v1sm[t] + v;
            else if (half == 0) out[(size_t)b * DOX + t] = v;
        }
        __syncthreads();
    }
    cluster_sync();   // keep smem alive until peer's last DSMEM read completes
}

// ---------------------------------------------------------------------------
extern "C" void kernel_launch(void* const* d_in, const int* in_sizes, int n_in,
                              void* d_out, int out_size) {
    const float* x = (const float*)d_in[0];   // [256, 1152, 8]
    const float* W = (const float*)d_in[1];   // [1, 10, 1152, 16, 8]
    float* out = (float*)d_out;               // [256, 10, 16]
    (void)in_sizes; (void)n_in; (void)out_size;

    k_uhat<<<dim3(NCH, NBG), DOX>>>(x, W);
    k_route<<<2 * BB, 256>>>(out);
}

// round 14
// speedup vs baseline: 1.0762x; 1.0030x over previous
#include <cuda_runtime.h>
#include <cuda_fp16.h>
#include <cstdint>

// Problem constants
#define BB 256
#define DD 10
#define PP 1152
#define OO 16
#define DOX 160            // D*O
#define II 8
#define PCH 8              // p per chunk in k_uhat
#define NCH (PP / PCH)     // 144
#define BGRP 64            // b per CTA in k_uhat
#define NBG (BB / BGRP)    // 4
#define HP (PP / 2)        // 576 p per cluster half
#define HCH (NCH / 2)      // 72 s1p chunks per half
#define NIT (HP / 16)      // 36 warp-iterations per pass (2 p per iter)
#define SEGL 6             // fp16 accumulation depth before fp32 flush

// Scratch (u_hat padded so prefetch past the end stays in-bounds)
__device__ __half g_uhat_h[(size_t)BB * PP * DOX + 64 * DOX];  // 94.4 MB
__device__ float g_s1p[(size_t)BB * NCH * DOX];                // 23.6 MB

// ---------------------------------------------------------------------------
// Kernel 1: u_hat = W.x (fp16 math + store) + per-chunk fp32 s1 partials.
// Grid (NCH, NBG) x 160 threads.  (round-10/11 version, ~23 us)
// ---------------------------------------------------------------------------
__global__ void __launch_bounds__(DOX) k_uhat(const float* __restrict__ x,
                                              const float* __restrict__ W) {
    const int c = blockIdx.x;
    const int t = threadIdx.x;
    const int d = t >> 4;
    const int o = t & 15;
    const int p0 = c * PCH;
    const int b0 = blockIdx.y * BGRP;

    __half2 w2[PCH][4];
#pragma unroll
    for (int ps = 0; ps < PCH; ps++) {
        const float4* wp = reinterpret_cast<const float4*>(
            W + (((size_t)d * PP + (size_t)(p0 + ps)) * OO + o) * II);
        float4 wa = wp[0], wb = wp[1];
        w2[ps][0] = __floats2half2_rn(wa.x, wa.y);
        w2[ps][1] = __floats2half2_rn(wa.z, wa.w);
        w2[ps][2] = __floats2half2_rn(wb.x, wb.y);
        w2[ps][3] = __floats2half2_rn(wb.z, wb.w);
    }

    __shared__ uint4 xs4[BGRP * PCH];   // 8 KB
    for (int idx = t; idx < BGRP * PCH; idx += DOX) {
        int bb = idx >> 3;
        int ps = idx & 7;
        const float4* xp = reinterpret_cast<const float4*>(
            x + ((size_t)(b0 + bb) * PP + (size_t)(p0 + ps)) * II);
        float4 xa = xp[0], xb = xp[1];
        uint4 h;
        reinterpret_cast<__half2*>(&h)[0] = __floats2half2_rn(xa.x, xa.y);
        reinterpret_cast<__half2*>(&h)[1] = __floats2half2_rn(xa.z, xa.w);
        reinterpret_cast<__half2*>(&h)[2] = __floats2half2_rn(xb.x, xb.y);
        reinterpret_cast<__half2*>(&h)[3] = __floats2half2_rn(xb.z, xb.w);
        xs4[idx] = h;
    }
    __syncthreads();

    for (int bb = 0; bb < BGRP; bb++) {
        float acc = 0.f;
        __half* ud = g_uhat_h + ((size_t)(b0 + bb) * PP + p0) * DOX + t;
#pragma unroll
        for (int ps = 0; ps < PCH; ps++) {
            uint4 xr = xs4[bb * PCH + ps];
            __half2 a = __hmul2(w2[ps][0], *reinterpret_cast<__half2*>(&xr.x));
            a = __hfma2(w2[ps][1], *reinterpret_cast<__half2*>(&xr.y), a);
            a = __hfma2(w2[ps][2], *reinterpret_cast<__half2*>(&xr.z), a);
            a = __hfma2(w2[ps][3], *reinterpret_cast<__half2*>(&xr.w), a);
            __half u = __hadd(__low2half(a), __high2half(a));
            ud[(size_t)ps * DOX] = u;
            acc += __half2float(u);
        }
        g_s1p[((size_t)(b0 + bb) * NCH + c) * DOX + t] = acc;
    }
}

// ---------------------------------------------------------------------------
// Helpers
// ---------------------------------------------------------------------------
__device__ __forceinline__ unsigned smem_u32(const void* p) {
    unsigned a;
    asm("{ .reg .u64 tmp; cvta.to.shared.u64 tmp, %1; cvt.u32.u64 %0, tmp; }"
        : "=r"(a) : "l"(p));
    return a;
}
__device__ __forceinline__ float ld_peer_f32(unsigned local_addr, unsigned rank) {
    unsigned ra;
    asm("mapa.shared::cluster.u32 %0, %1, %2;" : "=r"(ra) : "r"(local_addr), "r"(rank));
    float v;
    asm volatile("ld.shared::cluster.f32 %0, [%1];" : "=f"(v) : "r"(ra));
    return v;
}
__device__ __forceinline__ void cluster_sync() {
    asm volatile("barrier.cluster.arrive.aligned;" ::: "memory");
    asm volatile("barrier.cluster.wait.aligned;" ::: "memory");
}
__device__ __forceinline__ float squash_scale16(float s) {
    float sq = s * s;
    sq += __shfl_xor_sync(0xffffffffu, sq, 1);
    sq += __shfl_xor_sync(0xffffffffu, sq, 2);
    sq += __shfl_xor_sync(0xffffffffu, sq, 4);
    sq += __shfl_xor_sync(0xffffffffu, sq, 8);
    return sq / ((1.f + sq) * sqrtf(sq + 1e-7f));
}
__device__ __forceinline__ float expp(float xv) {
    float r = fmaf(xv, 1.f / 24.f, 1.f / 6.f);
    r = fmaf(r, xv, 0.5f);
    r = fmaf(r, xv, 1.f);
    r = fmaf(r, xv, 1.f);
    return r;
}
__device__ __forceinline__ void unp8(__half2* u, uint4 ra, uint4 rb) {
    u[0] = *reinterpret_cast<const __half2*>(&ra.x);
    u[1] = *reinterpret_cast<const __half2*>(&ra.y);
    u[2] = *reinterpret_cast<const __half2*>(&ra.z);
    u[3] = *reinterpret_cast<const __half2*>(&ra.w);
    u[4] = *reinterpret_cast<const __half2*>(&rb.x);
    u[5] = *reinterpret_cast<const __half2*>(&rb.y);
    u[6] = *reinterpret_cast<const __half2*>(&rb.z);
    u[7] = *reinterpret_cast<const __half2*>(&rb.w);
}
__device__ __forceinline__ float dot16(const __half2* u, const __half2* vh) {
    __half2 h0 = __hmul2(u[0], vh[0]);
    __half2 h1 = __hmul2(u[1], vh[1]);
    h0 = __hfma2(u[2], vh[2], h0);
    h1 = __hfma2(u[3], vh[3], h1);
    h0 = __hfma2(u[4], vh[4], h0);
    h1 = __hfma2(u[5], vh[5], h1);
    h0 = __hfma2(u[6], vh[6], h0);
    h1 = __hfma2(u[7], vh[7], h1);
    float2 hf = __half22float2(__hadd2(h0, h1));
    return hf.x + hf.y;
}

// ---------------------------------------------------------------------------
// Kernel 2: fused routing, 2-CTA cluster per b. R11 memory pattern (single
// stream, rows +16, 1-step prefetch). Software-pipelined: iteration k's
// dot/exp overlaps iteration k-1's softmax butterfly. Accumulators flushed
// to a per-(warp,ph) smem slab every SEGL iterations.
// Grid 2*BB x 256 threads.
// ---------------------------------------------------------------------------
__global__ void __launch_bounds__(256, 4) __cluster_dims__(2, 1, 1)
k_route(float* __restrict__ out) {
    const int b = blockIdx.x >> 1;
    const unsigned half = blockIdx.x & 1;
    const unsigned peer = half ^ 1u;
    const int t = threadIdx.x;
    const int lane = t & 31;
    const int wid = t >> 5;              // 0..7
    const int ph = lane >> 4;            // p parity within warp
    const int d = lane & 15;
    const bool valid = d < DD;
    const int dd = valid ? d : 0;
    const int row = wid * 2 + ph;        // 0..15 slab row

    __shared__ float vsm[DOX];
    __shared__ float v1sm[DOX];
    __shared__ float sred[16 * DOX];     // 10 KB
    __shared__ float xbuf[3][DOX];

    // ---- stage 0: v1 from s1p (my half of chunks) ----
    {
        float s = 0.f;
        if (t < DOX) {
            const float* sp = g_s1p + ((size_t)b * NCH + half * HCH) * DOX + t;
#pragma unroll 4
            for (int c = 0; c < HCH; c++) s += sp[(size_t)c * DOX];
            xbuf[0][t] = s;
        }
        cluster_sync();
        if (t < DOX) {
            float tot = s + ld_peer_f32(smem_u32(&xbuf[0][t]), peer);
            tot *= 0.1f;
            float v = tot * squash_scale16(tot);
            v1sm[t] = v;
            vsm[t] = v;
        }
        __syncthreads();
    }

    const __half* ulane = g_uhat_h + ((size_t)b * PP + (size_t)half * HP
                                      + (size_t)row) * DOX + dd * OO;
    const __half2 hzero = __half2half2(__ushort_as_half((unsigned short)0));

    for (int pass = 0; pass < 2; pass++) {
        __half2 vh[8];
#pragma unroll
        for (int j = 0; j < 8; j++)
            vh[j] = __floats2half2_rn(vsm[dd * OO + 2 * j], vsm[dd * OO + 2 * j + 1]);

        float4* slab = reinterpret_cast<float4*>(&sred[row * DOX + dd * OO]);

        // --- pipeline prologue: iteration 0's dot/exp ---
        const __half* up = ulane;
        uint4 ra = *reinterpret_cast<const uint4*>(up);
        uint4 rb = *reinterpret_cast<const uint4*>(up + 8);
        __half2 uP[8];
        unp8(uP, ra, rb);
        float eP = valid ? expp(dot16(uP, vh)) : 0.f;
        up += 16 * DOX;
        ra = *reinterpret_cast<const uint4*>(up);
        rb = *reinterpret_cast<const uint4*>(up + 8);

        __half2 sa16[8];
#pragma unroll
        for (int j = 0; j < 8; j++) sa16[j] = hzero;
        bool firstflush = true;

#pragma unroll
        for (int k = 1; k <= NIT; k++) {
            // butterfly on e_{k-1} (shuffle pipe) ...
            float tot = eP;
            tot += __shfl_xor_sync(0xffffffffu, tot, 1);
            tot += __shfl_xor_sync(0xffffffffu, tot, 2);
            tot += __shfl_xor_sync(0xffffffffu, tot, 4);
            tot += __shfl_xor_sync(0xffffffffu, tot, 8);

            // ... overlapped with iteration k's dot/exp (fma pipe)
            __half2 uC[8];
            float e = 0.f;
            if (k < NIT) {
                unp8(uC, ra, rb);
                float uv = dot16(uC, vh);
                e = valid ? expp(uv) : 0.f;
                up += 16 * DOX;
                ra = *reinterpret_cast<const uint4*>(up);   // padded: safe
                rb = *reinterpret_cast<const uint4*>(up + 8);
            }

            // finish iteration k-1
            float cc = __fdividef(eP, tot);
            __half2 cch = __half2half2(__float2half_rn(cc));
#pragma unroll
            for (int j = 0; j < 8; j++) sa16[j] = __hfma2(cch, uP[j], sa16[j]);

            // rotate (renamed under full unroll)
#pragma unroll
            for (int j = 0; j < 8; j++) uP[j] = uC[j];
            eP = e;

            if ((k % SEGL) == 0) {
                if (valid) {
                    float2 f0 = __half22float2(sa16[0]), f1 = __half22float2(sa16[1]);
                    float2 f2 = __half22float2(sa16[2]), f3 = __half22float2(sa16[3]);
                    float2 f4 = __half22float2(sa16[4]), f5 = __half22float2(sa16[5]);
                    float2 f6 = __half22float2(sa16[6]), f7 = __half22float2(sa16[7]);
                    float4 a0 = make_float4(f0.x, f0.y, f1.x, f1.y);
                    float4 a1 = make_float4(f2.x, f2.y, f3.x, f3.y);
                    float4 a2 = make_float4(f4.x, f4.y, f5.x, f5.y);
                    float4 a3 = make_float4(f6.x, f6.y, f7.x, f7.y);
                    if (firstflush) {
                        slab[0] = a0; slab[1] = a1; slab[2] = a2; slab[3] = a3;
                    } else {
                        float4 b0 = slab[0], b1 = slab[1], b2 = slab[2], b3 = slab[3];
                        slab[0] = make_float4(b0.x + a0.x, b0.y + a0.y, b0.z + a0.z, b0.w + a0.w);
                        slab[1] = make_float4(b1.x + a1.x, b1.y + a1.y, b1.z + a1.z, b1.w + a1.w);
                        slab[2] = make_float4(b2.x + a2.x, b2.y + a2.y, b2.z + a2.z, b2.w + a2.w);
                        slab[3] = make_float4(b3.x + a3.x, b3.y + a3.y, b3.z + a3.z, b3.w + a3.w);
                    }
                }
                firstflush = false;
#pragma unroll
                for (int j = 0; j < 8; j++) sa16[j] = hzero;
            }
        }
        __syncthreads();

        float s = 0.f;
        if (t < DOX) {
#pragma unroll
            for (int ww = 0; ww < 16; ww++) s += sred[ww * DOX + t];
            xbuf[pass + 1][t] = s;
        }
        cluster_sync();
        if (t < DOX) {
            float tot = s + ld_peer_f32(smem_u32(&xbuf[pass + 1][t]), peer);
            float v = tot * squash_scale16(tot);
            if (pass == 0) vsm[t] = v1sm[t] + v;
            else if (half == 0) out[(size_t)b * DOX + t] = v;
        }
        __syncthreads();
    }
    cluster_sync();   // keep smem alive until peer's last DSMEM read completes
}

// ---------------------------------------------------------------------------
extern "C" void kernel_launch(void* const* d_in, const int* in_sizes, int n_in,
                              void* d_out, int out_size) {
    const float* x = (const float*)d_in[0];   // [256, 1152, 8]
    const float* W = (const float*)d_in[1];   // [1, 10, 1152, 16, 8]
    float* out = (float*)d_out;               // [256, 10, 16]
    (void)in_sizes; (void)n_in; (void)out_size;

    k_uhat<<<dim3(NCH, NBG), DOX>>>(x, W);
    k_route<<<2 * BB, 256>>>(out);
}

// round 15
// speedup vs baseline: 1.1568x; 1.0749x over previous
#include <cuda_runtime.h>
#include <cuda_fp16.h>
#include <cstdint>

// Problem constants
#define BB 256
#define DD 10
#define PP 1152
#define OO 16
#define DOX 160            // D*O
#define II 8
#define PCH 8              // p per chunk in k_uhat
#define NCH (PP / PCH)     // 144
#define BGRP 64            // b per CTA in k_uhat
#define NBG (BB / BGRP)    // 4
#define HP (PP / 2)        // 576 p per cluster half
#define HCH (NCH / 2)      // 72 s1p chunks per half
#define NIT (HP / 16)      // 36 warp-iterations per pass (2 p per iter)

// Scratch (u_hat padded 64 rows so depth-2 prefetch stays in-bounds)
__device__ __half g_uhat_h[(size_t)BB * PP * DOX + 64 * DOX];  // 94.4 MB
__device__ float g_s1p[(size_t)BB * NCH * DOX];                // 23.6 MB

// ---------------------------------------------------------------------------
// Kernel 1: u_hat = W.x (fp16 math + store) + per-chunk fp32 s1 partials.
// Grid (NCH, NBG) x 160 threads.  (~23 us, validated)
// ---------------------------------------------------------------------------
__global__ void __launch_bounds__(DOX) k_uhat(const float* __restrict__ x,
                                              const float* __restrict__ W) {
    const int c = blockIdx.x;
    const int t = threadIdx.x;
    const int d = t >> 4;
    const int o = t & 15;
    const int p0 = c * PCH;
    const int b0 = blockIdx.y * BGRP;

    __half2 w2[PCH][4];
#pragma unroll
    for (int ps = 0; ps < PCH; ps++) {
        const float4* wp = reinterpret_cast<const float4*>(
            W + (((size_t)d * PP + (size_t)(p0 + ps)) * OO + o) * II);
        float4 wa = wp[0], wb = wp[1];
        w2[ps][0] = __floats2half2_rn(wa.x, wa.y);
        w2[ps][1] = __floats2half2_rn(wa.z, wa.w);
        w2[ps][2] = __floats2half2_rn(wb.x, wb.y);
        w2[ps][3] = __floats2half2_rn(wb.z, wb.w);
    }

    __shared__ uint4 xs4[BGRP * PCH];   // 8 KB
    for (int idx = t; idx < BGRP * PCH; idx += DOX) {
        int bb = idx >> 3;
        int ps = idx & 7;
        const float4* xp = reinterpret_cast<const float4*>(
            x + ((size_t)(b0 + bb) * PP + (size_t)(p0 + ps)) * II);
        float4 xa = xp[0], xb = xp[1];
        uint4 h;
        reinterpret_cast<__half2*>(&h)[0] = __floats2half2_rn(xa.x, xa.y);
        reinterpret_cast<__half2*>(&h)[1] = __floats2half2_rn(xa.z, xa.w);
        reinterpret_cast<__half2*>(&h)[2] = __floats2half2_rn(xb.x, xb.y);
        reinterpret_cast<__half2*>(&h)[3] = __floats2half2_rn(xb.z, xb.w);
        xs4[idx] = h;
    }
    __syncthreads();

    for (int bb = 0; bb < BGRP; bb++) {
        float acc = 0.f;
        __half* ud = g_uhat_h + ((size_t)(b0 + bb) * PP + p0) * DOX + t;
#pragma unroll
        for (int ps = 0; ps < PCH; ps++) {
            uint4 xr = xs4[bb * PCH + ps];
            __half2 a = __hmul2(w2[ps][0], *reinterpret_cast<__half2*>(&xr.x));
            a = __hfma2(w2[ps][1], *reinterpret_cast<__half2*>(&xr.y), a);
            a = __hfma2(w2[ps][2], *reinterpret_cast<__half2*>(&xr.z), a);
            a = __hfma2(w2[ps][3], *reinterpret_cast<__half2*>(&xr.w), a);
            __half u = __hadd(__low2half(a), __high2half(a));
            ud[(size_t)ps * DOX] = u;
            acc += __half2float(u);
        }
        g_s1p[((size_t)(b0 + bb) * NCH + c) * DOX + t] = acc;
    }
}

// ---------------------------------------------------------------------------
// Helpers
// ---------------------------------------------------------------------------
__device__ __forceinline__ unsigned smem_u32(const void* p) {
    unsigned a;
    asm("{ .reg .u64 tmp; cvta.to.shared.u64 tmp, %1; cvt.u32.u64 %0, tmp; }"
        : "=r"(a) : "l"(p));
    return a;
}
__device__ __forceinline__ float ld_peer_f32(unsigned local_addr, unsigned rank) {
    unsigned ra;
    asm("mapa.shared::cluster.u32 %0, %1, %2;" : "=r"(ra) : "r"(local_addr), "r"(rank));
    float v;
    asm volatile("ld.shared::cluster.f32 %0, [%1];" : "=f"(v) : "r"(ra));
    return v;
}
__device__ __forceinline__ void cluster_sync() {
    asm volatile("barrier.cluster.arrive.aligned;" ::: "memory");
    asm volatile("barrier.cluster.wait.aligned;" ::: "memory");
}
__device__ __forceinline__ float squash_scale16(float s) {
    float sq = s * s;
    sq += __shfl_xor_sync(0xffffffffu, sq, 1);
    sq += __shfl_xor_sync(0xffffffffu, sq, 2);
    sq += __shfl_xor_sync(0xffffffffu, sq, 4);
    sq += __shfl_xor_sync(0xffffffffu, sq, 8);
    return sq / ((1.f + sq) * sqrtf(sq + 1e-7f));
}
__device__ __forceinline__ float expp(float xv) {
    float r = fmaf(xv, 1.f / 24.f, 1.f / 6.f);
    r = fmaf(r, xv, 0.5f);
    r = fmaf(r, xv, 1.f);
    r = fmaf(r, xv, 1.f);
    return r;
}
__device__ __forceinline__ void unp8(__half2* u, uint4 ra, uint4 rb) {
    u[0] = *reinterpret_cast<const __half2*>(&ra.x);
    u[1] = *reinterpret_cast<const __half2*>(&ra.y);
    u[2] = *reinterpret_cast<const __half2*>(&ra.z);
    u[3] = *reinterpret_cast<const __half2*>(&ra.w);
    u[4] = *reinterpret_cast<const __half2*>(&rb.x);
    u[5] = *reinterpret_cast<const __half2*>(&rb.y);
    u[6] = *reinterpret_cast<const __half2*>(&rb.z);
    u[7] = *reinterpret_cast<const __half2*>(&rb.w);
}
__device__ __forceinline__ float dot16(const __half2* u, const __half2* vh) {
    __half2 h0 = __hmul2(u[0], vh[0]);
    __half2 h1 = __hmul2(u[1], vh[1]);
    h0 = __hfma2(u[2], vh[2], h0);
    h1 = __hfma2(u[3], vh[3], h1);
    h0 = __hfma2(u[4], vh[4], h0);
    h1 = __hfma2(u[5], vh[5], h1);
    h0 = __hfma2(u[6], vh[6], h0);
    h1 = __hfma2(u[7], vh[7], h1);
    float2 hf = __half22float2(__hadd2(h0, h1));
    return hf.x + hf.y;
}

// ---------------------------------------------------------------------------
// Kernel 2: fused routing, 2-CTA cluster per b. R11 loop structure with
// prefetch distance 2 (3 rotating register buffers). fp32 inter-segment
// accumulators live in thread-private padded smem (stride 17, conflict-free).
// Grid 2*BB x 256 threads.
// ---------------------------------------------------------------------------
__global__ void __launch_bounds__(256, 4) __cluster_dims__(2, 1, 1)
k_route(float* __restrict__ out) {
    const int b = blockIdx.x >> 1;
    const unsigned half = blockIdx.x & 1;
    const unsigned peer = half ^ 1u;
    const int t = threadIdx.x;
    const int lane = t & 31;
    const int wid = t >> 5;              // 0..7
    const int ph = lane >> 4;            // p parity within warp
    const int d = lane & 15;
    const bool valid = d < DD;
    const int dd = valid ? d : 0;

    __shared__ float vsm[DOX];
    __shared__ float v1sm[DOX];
    __shared__ float sred[8 * DOX];      // 5 KB
    __shared__ float xbuf[3][DOX];
    __shared__ float safm[256 * 17];     // 17 KB, thread-private fp32 accum

    // ---- stage 0: v1 from s1p (my half of chunks) ----
    {
        float s = 0.f;
        if (t < DOX) {
            const float* sp = g_s1p + ((size_t)b * NCH + half * HCH) * DOX + t;
#pragma unroll 8
            for (int c = 0; c < HCH; c++) s += sp[(size_t)c * DOX];
            xbuf[0][t] = s;
        }
        cluster_sync();
        if (t < DOX) {
            float tot = s + ld_peer_f32(smem_u32(&xbuf[0][t]), peer);
            tot *= 0.1f;
            float v = tot * squash_scale16(tot);
            v1sm[t] = v;
            vsm[t] = v;
        }
        __syncthreads();
    }

    const __half* ulane = g_uhat_h + ((size_t)b * PP + (size_t)half * HP
                                      + (size_t)(wid * 2 + ph)) * DOX + dd * OO;
    const __half2 hzero = __half2half2(__ushort_as_half((unsigned short)0));
    float* saf = &safm[t * 17];

    for (int pass = 0; pass < 2; pass++) {
        __half2 vh[8];
#pragma unroll
        for (int j = 0; j < 8; j++)
            vh[j] = __floats2half2_rn(vsm[dd * OO + 2 * j], vsm[dd * OO + 2 * j + 1]);

        // zero fp32 accumulators in smem
#pragma unroll
        for (int j = 0; j < 16; j++) saf[j] = 0.f;

        // prologue: preload iterations 0 and 1
        uint4 A[3], B[3];
        A[0] = *reinterpret_cast<const uint4*>(ulane);
        B[0] = *reinterpret_cast<const uint4*>(ulane + 8);
        A[1] = *reinterpret_cast<const uint4*>(ulane + 16 * DOX);
        B[1] = *reinterpret_cast<const uint4*>(ulane + 16 * DOX + 8);

        __half2 sa16[8];
#pragma unroll
        for (int j = 0; j < 8; j++) sa16[j] = hzero;

#pragma unroll 6
        for (int k = 0; k < NIT; k++) {
            const int cur = k % 3;
            const int nxt = (k + 2) % 3;
            // prefetch iteration k+2 (distance 2; padded tail -> safe)
            const __half* pup = ulane + (size_t)(k + 2) * 16 * DOX;
            A[nxt] = *reinterpret_cast<const uint4*>(pup);
            B[nxt] = *reinterpret_cast<const uint4*>(pup + 8);

            __half2 u2[8];
            unp8(u2, A[cur], B[cur]);

            float uv = dot16(u2, vh);
            float e = valid ? expp(uv) : 0.f;
            float tot = e;
            tot += __shfl_xor_sync(0xffffffffu, tot, 1);
            tot += __shfl_xor_sync(0xffffffffu, tot, 2);
            tot += __shfl_xor_sync(0xffffffffu, tot, 4);
            tot += __shfl_xor_sync(0xffffffffu, tot, 8);
            float cc = __fdividef(e, tot);

            __half2 cch = __half2half2(__float2half_rn(cc));
#pragma unroll
            for (int j = 0; j < 8; j++) sa16[j] = __hfma2(cch, u2[j], sa16[j]);

            // flush fp16 segment to fp32 smem accumulators every 6 iters
            if ((k % 6) == 5) {
#pragma unroll
                for (int j = 0; j < 8; j++) {
                    float2 f = __half22float2(sa16[j]);
                    saf[2 * j] += f.x;
                    saf[2 * j + 1] += f.y;
                    sa16[j] = hzero;
                }
            }
        }

        // epilogue: pull accumulators back, combine ph halves, publish
        float fa[16];
#pragma unroll
        for (int j = 0; j < 16; j++) fa[j] = saf[j];
#pragma unroll
        for (int j = 0; j < 16; j++) fa[j] += __shfl_xor_sync(0xffffffffu, fa[j], 16);
        if (ph == 0 && valid) {
#pragma unroll
            for (int j = 0; j < 16; j++) sred[wid * DOX + d * OO + j] = fa[j];
        }
        __syncthreads();

        float s = 0.f;
        if (t < DOX) {
#pragma unroll
            for (int ww = 0; ww < 8; ww++) s += sred[ww * DOX + t];
            xbuf[pass + 1][t] = s;
        }
        cluster_sync();
        if (t < DOX) {
            float tot = s + ld_peer_f32(smem_u32(&xbuf[pass + 1][t]), peer);
            float v = tot * squash_scale16(tot);
            if (pass == 0) vsm[t] = v1sm[t] + v;
            else if (half == 0) out[(size_t)b * DOX + t] = v;
        }
        __syncthreads();
    }
    cluster_sync();   // keep smem alive until peer's last DSMEM read completes
}

// ---------------------------------------------------------------------------
extern "C" void kernel_launch(void* const* d_in, const int* in_sizes, int n_in,
                              void* d_out, int out_size) {
    const float* x = (const float*)d_in[0];   // [256, 1152, 8]
    const float* W = (const float*)d_in[1];   // [1, 10, 1152, 16, 8]
    float* out = (float*)d_out;               // [256, 10, 16]
    (void)in_sizes; (void)n_in; (void)out_size;

    k_uhat<<<dim3(NCH, NBG), DOX>>>(x, W);
    k_route<<<2 * BB, 256>>>(out);
}